// round 9
// baseline (speedup 1.0000x reference)
#include <cuda_runtime.h>
#include <cuda_fp16.h>
#include <cstdint>
#include <cstddef>

// ============================================================================
// out[8192,4096] = SwiGLU-MLP(x[8192,4096]) with ternary weights.
// mma.sync m16n8k16 fp16->fp32 (compute_100 PTX: no tcgen05 available).
//
// History: R4 6640 -> R6 6461 (fused gate+up) -> R7 6200 (2 CTA/SM, 1 cvt)
// -> R8 5948 (GEMM2 retile 128x128/warp32x64, ~400 TF/s).
// This round: GEMM1-only retile -> CTA 256Mx64N, 512 thr / 16 warps (8m x 2n),
// same proven 32x32-per-matrix warp microkernel. Cuts GEMM1 L2->SMEM traffic
// 25% (0.031 -> 0.023 B/MAC) and halves its CTA count (prologue/epilogue
// events), at 1 CTA/SM (144 KB smem). GEMM2 + cvt unchanged from R8.
// ============================================================================
#define HID   4096
#define INTER 11008
#define MTOK  8192

// ============================================================================
// Device scratch (allocation rule: __device__ globals only)
// ============================================================================
__device__ __half g_x16 [(size_t)MTOK  * HID];     //  64 MB
__device__ __half g_wg16[(size_t)INTER * HID];     //  86 MB
__device__ __half g_wu16[(size_t)INTER * HID];     //  86 MB
__device__ __half g_wd16[(size_t)HID   * INTER];   //  86 MB
__device__ __half g_h16 [(size_t)MTOK  * INTER];   // 172 MB

// ============================================================================
// PTX helpers (sm_100-baseline: cp.async, ldmatrix, mma.sync)
// ============================================================================
__device__ __forceinline__ uint32_t smem_u32(const void* p) {
    uint32_t a;
    asm("{ .reg .u64 t; cvta.to.shared.u64 t, %1; cvt.u32.u64 %0, t; }"
        : "=r"(a) : "l"(p));
    return a;
}

__device__ __forceinline__ void cp_async16(uint32_t s, const void* g) {
    asm volatile("cp.async.cg.shared.global [%0], [%1], 16;" :: "r"(s), "l"(g));
}
#define CP_COMMIT() asm volatile("cp.async.commit_group;" ::: "memory")
#define CP_WAIT1()  asm volatile("cp.async.wait_group 1;"  ::: "memory")
#define CP_WAIT2()  asm volatile("cp.async.wait_group 2;"  ::: "memory")

__device__ __forceinline__ void ldsm4(uint32_t* r, uint32_t addr) {
    asm volatile("ldmatrix.sync.aligned.m8n8.x4.shared.b16 {%0,%1,%2,%3}, [%4];"
        : "=r"(r[0]), "=r"(r[1]), "=r"(r[2]), "=r"(r[3]) : "r"(addr));
}

__device__ __forceinline__ void mma16816(float* c, const uint32_t* a,
                                         uint32_t b0, uint32_t b1) {
    asm volatile(
        "mma.sync.aligned.m16n8k16.row.col.f32.f16.f16.f32 "
        "{%0,%1,%2,%3}, {%4,%5,%6,%7}, {%8,%9}, {%0,%1,%2,%3};"
        : "+f"(c[0]), "+f"(c[1]), "+f"(c[2]), "+f"(c[3])
        : "r"(a[0]), "r"(a[1]), "r"(a[2]), "r"(a[3]), "r"(b0), "r"(b1));
}

// ============================================================================
// Tile loader: R rows x 64 halves (128 B) per row, XOR-swizzled smem layout.
// smem_off = row*128 + ((chunk ^ (row&7)) << 4). Conflict-free for both the
// cp.async stores and ldmatrix reads. Verified correct in R4/R6/R7/R8.
// ============================================================================
template<int THREADS, int R>
__device__ __forceinline__ void load_tile(uint32_t sbase, const __half* g,
                                          int row0, int k0, int ldk) {
    int t = threadIdx.x;
    #pragma unroll
    for (int i = 0; i < R * 8 / THREADS; i++) {
        int ch = t + i * THREADS;
        int r = ch >> 3, c = ch & 7;
        cp_async16(sbase + r * 128 + (uint32_t)((c ^ (r & 7)) << 4),
                   g + (size_t)(row0 + r) * ldk + k0 + c * 8);
    }
}

__device__ __forceinline__ float sigmoidf_fast(float v) {
    return 1.0f / (1.0f + __expf(-v));
}

// ============================================================================
// Fused gate+up GEMM + SwiGLU.  CTA tile 256(M) x 64(N), BOTH matrices.
// 512 threads = 16 warps (8m x 2n), warp tile 32x32 per matrix (64 acc regs).
// 3-stage cp.async pipeline, stage = 48 KB (A 32K + Wg 8K + Wu 8K) = 144 KB
// -> 1 CTA/SM, 128 regs/thread budget. Prefetch issued BEFORE the wait so
// cp.async issue overlaps stage completion.
// Grid: x = m-tile (fast) so x (64 MB fp16) stays L2-resident.
// ============================================================================
#define STG1 49152u
#define SMEM1 (3 * 49152)

__global__ void __launch_bounds__(512, 1)
gemm1_fused(const __half* __restrict__ X, const __half* __restrict__ WG,
            const __half* __restrict__ WU, const float* __restrict__ ag,
            const float* __restrict__ au, __half* __restrict__ H) {
    extern __shared__ char smem[];
    const uint32_t sb = smem_u32(smem);
    const int m0 = blockIdx.x * 256;
    const int n0 = blockIdx.y * 64;
    const int l   = threadIdx.x & 31;
    const int wid = threadIdx.x >> 5;
    const int wm = (wid & 7) * 32;       // 8 m-positions
    const int wn = (wid >> 3) * 32;      // 2 n-positions
    const int KT = HID >> 6;             // 64

    #pragma unroll
    for (int s = 0; s < 2; s++) {
        uint32_t base = sb + (uint32_t)s * STG1;
        load_tile<512, 256>(base,           X,  m0, s * 64, HID);
        load_tile<512, 64> (base + 32768u,  WG, n0, s * 64, HID);
        load_tile<512, 64> (base + 40960u,  WU, n0, s * 64, HID);
        CP_COMMIT();
    }

    float accg[2][4][4], accu[2][4][4];
    #pragma unroll
    for (int i = 0; i < 2; i++)
        #pragma unroll
        for (int j = 0; j < 4; j++)
            #pragma unroll
            for (int q = 0; q < 4; q++) { accg[i][j][q] = 0.f; accu[i][j][q] = 0.f; }

    const int lr = l & 15, lc = l >> 4, lx = l & 7;

    int st = 0;
    for (int kt = 0; kt < KT; kt++) {
        // Issue prefetch of stage kt+2 FIRST (3 groups in flight), then wait
        // until <=2 pending, which guarantees stage kt has landed.
        if (kt + 2 < KT) {
            uint32_t base2 = sb + (uint32_t)((kt + 2) % 3) * STG1;
            load_tile<512, 256>(base2,          X,  m0, (kt + 2) * 64, HID);
            load_tile<512, 64> (base2 + 32768u, WG, n0, (kt + 2) * 64, HID);
            load_tile<512, 64> (base2 + 40960u, WU, n0, (kt + 2) * 64, HID);
        }
        CP_COMMIT();
        CP_WAIT2();
        __syncthreads();

        const uint32_t a_base = sb + (uint32_t)st * STG1           + (uint32_t)(wm + lr) * 128u;
        const uint32_t g_base = sb + (uint32_t)st * STG1 + 32768u  + (uint32_t)(wn + lr) * 128u;
        const uint32_t u_base = sb + (uint32_t)st * STG1 + 40960u  + (uint32_t)(wn + lr) * 128u;

        #pragma unroll
        for (int ks = 0; ks < 4; ks++) {
            const uint32_t ca = (uint32_t)(((ks * 2 + lc) ^ lx) << 4);
            uint32_t av[2][4], bg[2][4], bu[2][4];
            ldsm4(av[0], a_base + ca);
            ldsm4(av[1], a_base + 2048u + ca);
            ldsm4(bg[0], g_base + ca);
            ldsm4(bg[1], g_base + 2048u + ca);
            ldsm4(bu[0], u_base + ca);
            ldsm4(bu[1], u_base + 2048u + ca);
            #pragma unroll
            for (int mt = 0; mt < 2; mt++)
                #pragma unroll
                for (int nb = 0; nb < 2; nb++) {
                    mma16816(accg[mt][nb * 2 + 0], av[mt], bg[nb][0], bg[nb][2]);
                    mma16816(accg[mt][nb * 2 + 1], av[mt], bg[nb][1], bg[nb][3]);
                    mma16816(accu[mt][nb * 2 + 0], av[mt], bu[nb][0], bu[nb][2]);
                    mma16816(accu[mt][nb * 2 + 1], av[mt], bu[nb][1], bu[nb][3]);
                }
        }
        // Sync before the NEXT iteration's prefetch overwrites stage (kt+2)%3
        // is unnecessary: that stage was consumed 1 iteration ago and the
        // barrier above already separated its readers from these writers.
        if (++st == 3) st = 0;
    }

    // SwiGLU epilogue -> fp16 h
    const int r0 = l >> 2, c0 = (l & 3) * 2;
    #pragma unroll
    for (int mt = 0; mt < 2; mt++) {
        int gm = m0 + wm + mt * 16 + r0;
        #pragma unroll
        for (int nf = 0; nf < 4; nf++) {
            int gn = n0 + wn + nf * 8 + c0;
            float sg0 = ag[gn], sg1 = ag[gn + 1];
            float su0 = au[gn], su1 = au[gn + 1];
            float* G = accg[mt][nf];
            float* U = accu[mt][nf];
            float g0 = G[0] * sg0, g1 = G[1] * sg1;
            float u0 = U[0] * su0, u1 = U[1] * su1;
            *reinterpret_cast<__half2*>(H + (size_t)gm * INTER + gn) =
                __floats2half2_rn(g0 * sigmoidf_fast(g0) * u0,
                                  g1 * sigmoidf_fast(g1) * u1);
            float g2 = G[2] * sg0, g3 = G[3] * sg1;
            float u2 = U[2] * su0, u3 = U[3] * su1;
            *reinterpret_cast<__half2*>(H + (size_t)(gm + 8) * INTER + gn) =
                __floats2half2_rn(g2 * sigmoidf_fast(g2) * u2,
                                  g3 * sigmoidf_fast(g3) * u3);
        }
    }
}

// ============================================================================
// GEMM2: out[m,n] = (sum_k h[m,k] * Wd[n,k]) * ad[n], fp32 out.
// CTA 128x128, 256 threads / 8 warps (4m x 2n), warp tile 32x64.
// 16 mma / 6 ldsm4 per k16-step. 3 stages x 32 KB = 96 KB -> 2 CTAs/SM.
// Grid: x = n-tile (fast) so Wd (86 MB) stays L2-resident; h streams once.
// (Unchanged from R8 — measured at ~400 TF/s.)
// ============================================================================
#define STG2 32768u
#define SMEM2 (3 * 32768)

__global__ void __launch_bounds__(256, 2)
gemm2_kernel(const __half* __restrict__ A, const __half* __restrict__ B,
             const float* __restrict__ ad, float* __restrict__ out) {
    extern __shared__ char smem[];
    const uint32_t sb = smem_u32(smem);
    const int n0 = blockIdx.x * 128;      // n fast: weight-resident policy
    const int m0 = blockIdx.y * 128;
    const int l   = threadIdx.x & 31;
    const int wid = threadIdx.x >> 5;
    const int wm = (wid & 3) * 32;        // 4 m-positions
    const int wn = (wid >> 2) * 64;       // 2 n-positions, 64 wide each
    const int KT = INTER >> 6;            // 172

    #pragma unroll
    for (int s = 0; s < 2; s++) {
        uint32_t base = sb + (uint32_t)s * STG2;
        load_tile<256, 128>(base,          A, m0, s * 64, INTER);
        load_tile<256, 128>(base + 16384u, B, n0, s * 64, INTER);
        CP_COMMIT();
    }

    float acc[2][8][4];
    #pragma unroll
    for (int i = 0; i < 2; i++)
        #pragma unroll
        for (int j = 0; j < 8; j++)
            #pragma unroll
            for (int q = 0; q < 4; q++) acc[i][j][q] = 0.f;

    const int lr = l & 15, lc = l >> 4, lx = l & 7;

    int st = 0;
    for (int kt = 0; kt < KT; kt++) {
        CP_WAIT1();
        __syncthreads();
        if (kt + 2 < KT) {
            uint32_t base2 = sb + (uint32_t)((kt + 2) % 3) * STG2;
            load_tile<256, 128>(base2,          A, m0, (kt + 2) * 64, INTER);
            load_tile<256, 128>(base2 + 16384u, B, n0, (kt + 2) * 64, INTER);
        }
        CP_COMMIT();

        const uint32_t a_base = sb + (uint32_t)st * STG2          + (uint32_t)(wm + lr) * 128u;
        const uint32_t b_base = sb + (uint32_t)st * STG2 + 16384u + (uint32_t)(wn + lr) * 128u;

        #pragma unroll
        for (int ks = 0; ks < 4; ks++) {
            const uint32_t ca = (uint32_t)(((ks * 2 + lc) ^ lx) << 4);
            uint32_t av[2][4], bv[4][4];
            ldsm4(av[0], a_base + ca);
            ldsm4(av[1], a_base + 2048u + ca);
            #pragma unroll
            for (int nb = 0; nb < 4; nb++)
                ldsm4(bv[nb], b_base + (uint32_t)nb * 2048u + ca);
            #pragma unroll
            for (int mt = 0; mt < 2; mt++)
                #pragma unroll
                for (int nb = 0; nb < 4; nb++) {
                    mma16816(acc[mt][nb * 2 + 0], av[mt], bv[nb][0], bv[nb][2]);
                    mma16816(acc[mt][nb * 2 + 1], av[mt], bv[nb][1], bv[nb][3]);
                }
        }
        if (++st == 3) st = 0;
    }

    const int r0 = l >> 2, c0 = (l & 3) * 2;
    #pragma unroll
    for (int mt = 0; mt < 2; mt++) {
        int gm = m0 + wm + mt * 16 + r0;
        #pragma unroll
        for (int nf = 0; nf < 8; nf++) {
            int gn = n0 + wn + nf * 8 + c0;
            float s0 = ad[gn], s1 = ad[gn + 1];
            float* a4 = acc[mt][nf];
            *reinterpret_cast<float2*>(out + (size_t)gm * HID + gn) =
                make_float2(a4[0] * s0, a4[1] * s1);
            *reinterpret_cast<float2*>(out + (size_t)(gm + 8) * HID + gn) =
                make_float2(a4[2] * s0, a4[3] * s1);
        }
    }
}

// ============================================================================
// Merged fp32 -> fp16 conversion: all four tensors in one launch.
// ============================================================================
__global__ void cvt_all(const float* __restrict__ i0, __half* __restrict__ o0, size_t n0,
                        const float* __restrict__ i1, __half* __restrict__ o1, size_t n1,
                        const float* __restrict__ i2, __half* __restrict__ o2, size_t n2,
                        const float* __restrict__ i3, __half* __restrict__ o3, size_t n3) {
    const size_t stride = (size_t)gridDim.x * blockDim.x;
    const size_t t0 = (size_t)blockIdx.x * blockDim.x + threadIdx.x;
    const float*  in[4]   = {i0, i1, i2, i3};
    __half*       outp[4] = {o0, o1, o2, o3};
    const size_t  n[4]    = {n0, n1, n2, n3};
    #pragma unroll
    for (int s = 0; s < 4; s++) {
        const float* src = in[s];
        __half* dst = outp[s];
        for (size_t i = t0; i < n[s]; i += stride) {
            float4 v = reinterpret_cast<const float4*>(src)[i];
            __half2 lo = __floats2half2_rn(v.x, v.y);
            __half2 hi = __floats2half2_rn(v.z, v.w);
            uint2 o;
            o.x = *reinterpret_cast<uint32_t*>(&lo);
            o.y = *reinterpret_cast<uint32_t*>(&hi);
            reinterpret_cast<uint2*>(dst)[i] = o;
        }
    }
}

// ============================================================================
// Host side
// ============================================================================
extern "C" void kernel_launch(void* const* d_in, const int* in_sizes, int n_in,
                              void* d_out, int out_size) {
    const float* x  = (const float*)d_in[0];
    const float* Wg = (const float*)d_in[1];
    const float* Wu = (const float*)d_in[2];
    const float* Wd = (const float*)d_in[3];
    const float* ag = (const float*)d_in[4];
    const float* au = (const float*)d_in[5];
    const float* ad = (const float*)d_in[6];
    float* out = (float*)d_out;

    void *px, *pwg, *pwu, *pwd, *ph;
    cudaGetSymbolAddress(&px,  g_x16);
    cudaGetSymbolAddress(&pwg, g_wg16);
    cudaGetSymbolAddress(&pwu, g_wu16);
    cudaGetSymbolAddress(&pwd, g_wd16);
    cudaGetSymbolAddress(&ph,  g_h16);

    cudaFuncSetAttribute(gemm1_fused,
                         cudaFuncAttributeMaxDynamicSharedMemorySize, SMEM1);
    cudaFuncSetAttribute(gemm2_kernel,
                         cudaFuncAttributeMaxDynamicSharedMemorySize, SMEM2);

    // All fp32 -> fp16 conversions in one launch
    cvt_all<<<3072, 256>>>(
        x,  (__half*)px,  (size_t)MTOK  * HID   / 4,
        Wg, (__half*)pwg, (size_t)INTER * HID   / 4,
        Wu, (__half*)pwu, (size_t)INTER * HID   / 4,
        Wd, (__half*)pwd, (size_t)HID   * INTER / 4);

    // Fused gate+up+SwiGLU -> h (fp16). m-tiles fast (x L2-resident).
    gemm1_fused<<<dim3(MTOK / 256, INTER / 64), 512, SMEM1>>>(
        (const __half*)px, (const __half*)pwg, (const __half*)pwu,
        ag, au, (__half*)ph);

    // out = (h @ Wd^T) * ad. n-tiles fast (Wd L2-resident).
    gemm2_kernel<<<dim3(HID / 128, MTOK / 128), 256, SMEM2>>>(
        (const __half*)ph, (const __half*)pwd, ad, out);
}

// round 10
// speedup vs baseline: 1.0241x; 1.0241x over previous
#include <cuda_runtime.h>
#include <cuda_fp16.h>
#include <cstdint>
#include <cstddef>

// ============================================================================
// out[8192,4096] = SwiGLU-MLP(x[8192,4096]) with ternary weights.
// mma.sync m16n8k16 fp16->fp32 (compute_100 PTX: no tcgen05 available).
//
// History: R4 6640 -> R6 6461 -> R7 6200 -> R8 5948 (best) -> R9 6084
// (256x64/1CTA-per-SM GEMM1 regressed: occupancy 2/SM beats tile traffic).
// This round: GEMM1 reverted to R8 exactly (128x64, 256thr, 2 CTA/SM);
// both GEMMs gain smem-staged coalesced epilogues (fragment stores were
// 4-8B per 32B sector; now 16B-chunk fully-coalesced global writes).
// GEMMs measured at 92-98% of the ~405 TF/s legacy-HMMA pipe ceiling.
// ============================================================================
#define HID   4096
#define INTER 11008
#define MTOK  8192

// ============================================================================
// Device scratch (allocation rule: __device__ globals only)
// ============================================================================
__device__ __half g_x16 [(size_t)MTOK  * HID];     //  64 MB
__device__ __half g_wg16[(size_t)INTER * HID];     //  86 MB
__device__ __half g_wu16[(size_t)INTER * HID];     //  86 MB
__device__ __half g_wd16[(size_t)HID   * INTER];   //  86 MB
__device__ __half g_h16 [(size_t)MTOK  * INTER];   // 172 MB

// ============================================================================
// PTX helpers (sm_100-baseline: cp.async, ldmatrix, mma.sync)
// ============================================================================
__device__ __forceinline__ uint32_t smem_u32(const void* p) {
    uint32_t a;
    asm("{ .reg .u64 t; cvta.to.shared.u64 t, %1; cvt.u32.u64 %0, t; }"
        : "=r"(a) : "l"(p));
    return a;
}

__device__ __forceinline__ void cp_async16(uint32_t s, const void* g) {
    asm volatile("cp.async.cg.shared.global [%0], [%1], 16;" :: "r"(s), "l"(g));
}
#define CP_COMMIT() asm volatile("cp.async.commit_group;" ::: "memory")
#define CP_WAIT1()  asm volatile("cp.async.wait_group 1;"  ::: "memory")

__device__ __forceinline__ void ldsm4(uint32_t* r, uint32_t addr) {
    asm volatile("ldmatrix.sync.aligned.m8n8.x4.shared.b16 {%0,%1,%2,%3}, [%4];"
        : "=r"(r[0]), "=r"(r[1]), "=r"(r[2]), "=r"(r[3]) : "r"(addr));
}

__device__ __forceinline__ void mma16816(float* c, const uint32_t* a,
                                         uint32_t b0, uint32_t b1) {
    asm volatile(
        "mma.sync.aligned.m16n8k16.row.col.f32.f16.f16.f32 "
        "{%0,%1,%2,%3}, {%4,%5,%6,%7}, {%8,%9}, {%0,%1,%2,%3};"
        : "+f"(c[0]), "+f"(c[1]), "+f"(c[2]), "+f"(c[3])
        : "r"(a[0]), "r"(a[1]), "r"(a[2]), "r"(a[3]), "r"(b0), "r"(b1));
}

// ============================================================================
// Tile loader: R rows x 64 halves (128 B) per row, XOR-swizzled smem layout.
// smem_off = row*128 + ((chunk ^ (row&7)) << 4). Conflict-free for both the
// cp.async stores and ldmatrix reads. Verified correct R4-R9.
// ============================================================================
template<int THREADS, int R>
__device__ __forceinline__ void load_tile(uint32_t sbase, const __half* g,
                                          int row0, int k0, int ldk) {
    int t = threadIdx.x;
    #pragma unroll
    for (int i = 0; i < R * 8 / THREADS; i++) {
        int ch = t + i * THREADS;
        int r = ch >> 3, c = ch & 7;
        cp_async16(sbase + r * 128 + (uint32_t)((c ^ (r & 7)) << 4),
                   g + (size_t)(row0 + r) * ldk + k0 + c * 8);
    }
}

__device__ __forceinline__ float sigmoidf_fast(float v) {
    return 1.0f / (1.0f + __expf(-v));
}

// ============================================================================
// Fused gate+up GEMM + SwiGLU.  CTA tile 128(M) x 64(N).  (R8 config.)
// 256 threads = 8 warps (4m x 2n), warp tile 32x32 per matrix.
// 3-stage cp.async pipeline, stage = 32 KB -> 96 KB -> 2 CTAs/SM.
// NEW: epilogue stages h through smem (row stride 144B, bank-safe) and
// writes global in coalesced 16B chunks.
// Grid: x = m-tile (fast) so x (64 MB fp16) stays L2-resident.
// ============================================================================
#define STG1 32768u
#define SMEM1 (3 * 32768)
#define EP1_STRIDE 144u   // 64 halves = 128B, +16B pad -> 4-bank row shift

__global__ void __launch_bounds__(256, 2)
gemm1_fused(const __half* __restrict__ X, const __half* __restrict__ WG,
            const __half* __restrict__ WU, const float* __restrict__ ag,
            const float* __restrict__ au, __half* __restrict__ H) {
    extern __shared__ char smem[];
    const uint32_t sb = smem_u32(smem);
    const int m0 = blockIdx.x * 128;
    const int n0 = blockIdx.y * 64;
    const int l   = threadIdx.x & 31;
    const int wid = threadIdx.x >> 5;
    const int wm = (wid & 3) * 32;
    const int wn = (wid >> 2) * 32;
    const int KT = HID >> 6;

    #pragma unroll
    for (int s = 0; s < 2; s++) {
        uint32_t base = sb + (uint32_t)s * STG1;
        load_tile<256, 128>(base,           X,  m0, s * 64, HID);
        load_tile<256, 64> (base + 16384u,  WG, n0, s * 64, HID);
        load_tile<256, 64> (base + 24576u,  WU, n0, s * 64, HID);
        CP_COMMIT();
    }

    float accg[2][4][4], accu[2][4][4];
    #pragma unroll
    for (int i = 0; i < 2; i++)
        #pragma unroll
        for (int j = 0; j < 4; j++)
            #pragma unroll
            for (int q = 0; q < 4; q++) { accg[i][j][q] = 0.f; accu[i][j][q] = 0.f; }

    const int lr = l & 15, lc = l >> 4, lx = l & 7;

    int st = 0;
    for (int kt = 0; kt < KT; kt++) {
        CP_WAIT1();
        __syncthreads();
        if (kt + 2 < KT) {
            uint32_t base2 = sb + (uint32_t)((kt + 2) % 3) * STG1;
            load_tile<256, 128>(base2,          X,  m0, (kt + 2) * 64, HID);
            load_tile<256, 64> (base2 + 16384u, WG, n0, (kt + 2) * 64, HID);
            load_tile<256, 64> (base2 + 24576u, WU, n0, (kt + 2) * 64, HID);
        }
        CP_COMMIT();

        const uint32_t a_base = sb + (uint32_t)st * STG1           + (uint32_t)(wm + lr) * 128u;
        const uint32_t g_base = sb + (uint32_t)st * STG1 + 16384u  + (uint32_t)(wn + lr) * 128u;
        const uint32_t u_base = sb + (uint32_t)st * STG1 + 24576u  + (uint32_t)(wn + lr) * 128u;

        #pragma unroll
        for (int ks = 0; ks < 4; ks++) {
            const uint32_t ca = (uint32_t)(((ks * 2 + lc) ^ lx) << 4);
            uint32_t av[2][4], bg[2][4], bu[2][4];
            ldsm4(av[0], a_base + ca);
            ldsm4(av[1], a_base + 2048u + ca);
            ldsm4(bg[0], g_base + ca);
            ldsm4(bg[1], g_base + 2048u + ca);
            ldsm4(bu[0], u_base + ca);
            ldsm4(bu[1], u_base + 2048u + ca);
            #pragma unroll
            for (int mt = 0; mt < 2; mt++)
                #pragma unroll
                for (int nb = 0; nb < 2; nb++) {
                    mma16816(accg[mt][nb * 2 + 0], av[mt], bg[nb][0], bg[nb][2]);
                    mma16816(accg[mt][nb * 2 + 1], av[mt], bg[nb][1], bg[nb][3]);
                    mma16816(accu[mt][nb * 2 + 0], av[mt], bu[nb][0], bu[nb][2]);
                    mma16816(accu[mt][nb * 2 + 1], av[mt], bu[nb][1], bu[nb][3]);
                }
        }
        if (++st == 3) st = 0;
    }

    // ---- SwiGLU epilogue: regs -> smem (padded) -> coalesced global ----
    __syncthreads();                    // mainloop smem reads done everywhere
    const int r0 = l >> 2, c0 = (l & 3) * 2;
    #pragma unroll
    for (int mt = 0; mt < 2; mt++) {
        int lrow = wm + mt * 16 + r0;   // local row 0..127
        #pragma unroll
        for (int nf = 0; nf < 4; nf++) {
            int lcol = wn + nf * 8 + c0;            // local col 0..63
            int gn = n0 + lcol;
            float sg0 = ag[gn], sg1 = ag[gn + 1];
            float su0 = au[gn], su1 = au[gn + 1];
            float* G = accg[mt][nf];
            float* U = accu[mt][nf];
            float g0 = G[0] * sg0, g1 = G[1] * sg1;
            float u0 = U[0] * su0, u1 = U[1] * su1;
            __half2 h01 = __floats2half2_rn(g0 * sigmoidf_fast(g0) * u0,
                                            g1 * sigmoidf_fast(g1) * u1);
            float g2 = G[2] * sg0, g3 = G[3] * sg1;
            float u2 = U[2] * su0, u3 = U[3] * su1;
            __half2 h23 = __floats2half2_rn(g2 * sigmoidf_fast(g2) * u2,
                                            g3 * sigmoidf_fast(g3) * u3);
            *reinterpret_cast<__half2*>(smem + (uint32_t)lrow * EP1_STRIDE + lcol * 2) = h01;
            *reinterpret_cast<__half2*>(smem + (uint32_t)(lrow + 8) * EP1_STRIDE + lcol * 2) = h23;
        }
    }
    __syncthreads();
    // copy out: 128 rows x 128B = 1024 x 16B chunks, 4 per thread, coalesced
    #pragma unroll
    for (int i = 0; i < 4; i++) {
        int ch = threadIdx.x + i * 256;
        int row = ch >> 3, c = ch & 7;
        uint4 v = *reinterpret_cast<const uint4*>(smem + (uint32_t)row * EP1_STRIDE + c * 16);
        *reinterpret_cast<uint4*>(H + (size_t)(m0 + row) * INTER + n0 + c * 8) = v;
    }
}

// ============================================================================
// GEMM2: out[m,n] = (sum_k h[m,k] * Wd[n,k]) * ad[n], fp32 out.  (R8 config.)
// CTA 128x128, 256 threads / 8 warps (4m x 2n), warp tile 32x64.
// 3 stages x 32 KB = 96 KB -> 2 CTAs/SM.
// NEW: smem-staged coalesced epilogue (row stride 528B, bank-safe).
// Grid: x = n-tile (fast) so Wd (86 MB) stays L2-resident; h streams once.
// ============================================================================
#define STG2 32768u
#define SMEM2 (3 * 32768)
#define EP2_STRIDE 528u   // 128 floats = 512B, +16B pad -> 4-bank row shift

__global__ void __launch_bounds__(256, 2)
gemm2_kernel(const __half* __restrict__ A, const __half* __restrict__ B,
             const float* __restrict__ ad, float* __restrict__ out) {
    extern __shared__ char smem[];
    const uint32_t sb = smem_u32(smem);
    const int n0 = blockIdx.x * 128;      // n fast: weight-resident policy
    const int m0 = blockIdx.y * 128;
    const int l   = threadIdx.x & 31;
    const int wid = threadIdx.x >> 5;
    const int wm = (wid & 3) * 32;        // 4 m-positions
    const int wn = (wid >> 2) * 64;       // 2 n-positions, 64 wide each
    const int KT = INTER >> 6;            // 172

    #pragma unroll
    for (int s = 0; s < 2; s++) {
        uint32_t base = sb + (uint32_t)s * STG2;
        load_tile<256, 128>(base,          A, m0, s * 64, INTER);
        load_tile<256, 128>(base + 16384u, B, n0, s * 64, INTER);
        CP_COMMIT();
    }

    float acc[2][8][4];
    #pragma unroll
    for (int i = 0; i < 2; i++)
        #pragma unroll
        for (int j = 0; j < 8; j++)
            #pragma unroll
            for (int q = 0; q < 4; q++) acc[i][j][q] = 0.f;

    const int lr = l & 15, lc = l >> 4, lx = l & 7;

    int st = 0;
    for (int kt = 0; kt < KT; kt++) {
        CP_WAIT1();
        __syncthreads();
        if (kt + 2 < KT) {
            uint32_t base2 = sb + (uint32_t)((kt + 2) % 3) * STG2;
            load_tile<256, 128>(base2,          A, m0, (kt + 2) * 64, INTER);
            load_tile<256, 128>(base2 + 16384u, B, n0, (kt + 2) * 64, INTER);
        }
        CP_COMMIT();

        const uint32_t a_base = sb + (uint32_t)st * STG2          + (uint32_t)(wm + lr) * 128u;
        const uint32_t b_base = sb + (uint32_t)st * STG2 + 16384u + (uint32_t)(wn + lr) * 128u;

        #pragma unroll
        for (int ks = 0; ks < 4; ks++) {
            const uint32_t ca = (uint32_t)(((ks * 2 + lc) ^ lx) << 4);
            uint32_t av[2][4], bv[4][4];
            ldsm4(av[0], a_base + ca);
            ldsm4(av[1], a_base + 2048u + ca);
            #pragma unroll
            for (int nb = 0; nb < 4; nb++)
                ldsm4(bv[nb], b_base + (uint32_t)nb * 2048u + ca);
            #pragma unroll
            for (int mt = 0; mt < 2; mt++)
                #pragma unroll
                for (int nb = 0; nb < 4; nb++) {
                    mma16816(acc[mt][nb * 2 + 0], av[mt], bv[nb][0], bv[nb][2]);
                    mma16816(acc[mt][nb * 2 + 1], av[mt], bv[nb][1], bv[nb][3]);
                }
        }
        if (++st == 3) st = 0;
    }

    // ---- epilogue: regs -> smem (padded) -> coalesced global ----
    __syncthreads();
    const int r0 = l >> 2, c0 = (l & 3) * 2;
    #pragma unroll
    for (int mt = 0; mt < 2; mt++) {
        int lrow = wm + mt * 16 + r0;    // 0..127
        #pragma unroll
        for (int nf = 0; nf < 8; nf++) {
            int lcol = wn + nf * 8 + c0; // 0..127
            int gn = n0 + lcol;
            float s0 = ad[gn], s1 = ad[gn + 1];
            float* a4 = acc[mt][nf];
            *reinterpret_cast<float2*>(smem + (uint32_t)lrow * EP2_STRIDE + lcol * 4) =
                make_float2(a4[0] * s0, a4[1] * s1);
            *reinterpret_cast<float2*>(smem + (uint32_t)(lrow + 8) * EP2_STRIDE + lcol * 4) =
                make_float2(a4[2] * s0, a4[3] * s1);
        }
    }
    __syncthreads();
    // copy out: 128 rows x 512B = 4096 x 16B chunks, 16 per thread, coalesced
    #pragma unroll
    for (int i = 0; i < 16; i++) {
        int ch = threadIdx.x + i * 256;
        int row = ch >> 5, c = ch & 31;
        uint4 v = *reinterpret_cast<const uint4*>(smem + (uint32_t)row * EP2_STRIDE + c * 16);
        *reinterpret_cast<uint4*>(out + (size_t)(m0 + row) * HID + n0 + c * 4) = v;
    }
}

// ============================================================================
// Merged fp32 -> fp16 conversion: all four tensors in one launch.
// ============================================================================
__global__ void cvt_all(const float* __restrict__ i0, __half* __restrict__ o0, size_t n0,
                        const float* __restrict__ i1, __half* __restrict__ o1, size_t n1,
                        const float* __restrict__ i2, __half* __restrict__ o2, size_t n2,
                        const float* __restrict__ i3, __half* __restrict__ o3, size_t n3) {
    const size_t stride = (size_t)gridDim.x * blockDim.x;
    const size_t t0 = (size_t)blockIdx.x * blockDim.x + threadIdx.x;
    const float*  in[4]   = {i0, i1, i2, i3};
    __half*       outp[4] = {o0, o1, o2, o3};
    const size_t  n[4]    = {n0, n1, n2, n3};
    #pragma unroll
    for (int s = 0; s < 4; s++) {
        const float* src = in[s];
        __half* dst = outp[s];
        for (size_t i = t0; i < n[s]; i += stride) {
            float4 v = reinterpret_cast<const float4*>(src)[i];
            __half2 lo = __floats2half2_rn(v.x, v.y);
            __half2 hi = __floats2half2_rn(v.z, v.w);
            uint2 o;
            o.x = *reinterpret_cast<uint32_t*>(&lo);
            o.y = *reinterpret_cast<uint32_t*>(&hi);
            reinterpret_cast<uint2*>(dst)[i] = o;
        }
    }
}

// ============================================================================
// Host side
// ============================================================================
extern "C" void kernel_launch(void* const* d_in, const int* in_sizes, int n_in,
                              void* d_out, int out_size) {
    const float* x  = (const float*)d_in[0];
    const float* Wg = (const float*)d_in[1];
    const float* Wu = (const float*)d_in[2];
    const float* Wd = (const float*)d_in[3];
    const float* ag = (const float*)d_in[4];
    const float* au = (const float*)d_in[5];
    const float* ad = (const float*)d_in[6];
    float* out = (float*)d_out;

    void *px, *pwg, *pwu, *pwd, *ph;
    cudaGetSymbolAddress(&px,  g_x16);
    cudaGetSymbolAddress(&pwg, g_wg16);
    cudaGetSymbolAddress(&pwu, g_wu16);
    cudaGetSymbolAddress(&pwd, g_wd16);
    cudaGetSymbolAddress(&ph,  g_h16);

    cudaFuncSetAttribute(gemm1_fused,
                         cudaFuncAttributeMaxDynamicSharedMemorySize, SMEM1);
    cudaFuncSetAttribute(gemm2_kernel,
                         cudaFuncAttributeMaxDynamicSharedMemorySize, SMEM2);

    // All fp32 -> fp16 conversions in one launch
    cvt_all<<<3072, 256>>>(
        x,  (__half*)px,  (size_t)MTOK  * HID   / 4,
        Wg, (__half*)pwg, (size_t)INTER * HID   / 4,
        Wu, (__half*)pwu, (size_t)INTER * HID   / 4,
        Wd, (__half*)pwd, (size_t)HID   * INTER / 4);

    // Fused gate+up+SwiGLU -> h (fp16). m-tiles fast (x L2-resident).
    gemm1_fused<<<dim3(MTOK / 128, INTER / 64), 256, SMEM1>>>(
        (const __half*)px, (const __half*)pwg, (const __half*)pwu,
        ag, au, (__half*)ph);

    // out = (h @ Wd^T) * ad. n-tiles fast (Wd L2-resident).
    gemm2_kernel<<<dim3(HID / 128, MTOK / 128), 256, SMEM2>>>(
        (const __half*)ph, (const __half*)pwd, ad, out);
}

// round 13
// speedup vs baseline: 1.0310x; 1.0067x over previous
#include <cuda_runtime.h>
#include <cuda_fp16.h>
#include <cstdint>
#include <cstddef>

// ============================================================================
// out[8192,4096] = SwiGLU-MLP(x[8192,4096]) with ternary weights.
// mma.sync m16n8k16 fp16->fp32 (compute_100 PTX: no tcgen05 available).
//
// History: R4 6640 -> R6 6461 -> R7 6200 -> R8 5948 -> R10 5941 (best).
// R11's stream-fork overlap broke graph capture; R12 (this design) hit broker
// infra failure — resubmitting unchanged. Capture-legal overlap: the Wd
// fp32->fp16 conversion rides INSIDE the gemm1 launch as 64 extra CTAs
// (blockIdx.y==0, first wave), overlapping the pipe-bound GEMM1. GEMM2 (same
// stream) waits for the whole launch, so Wd is ready. cvt shrinks to x/Wg/Wu
// only. GEMM mainloops unchanged (~93% of the ~403 TF/s legacy HMMA issue
// ceiling; retiles blocked by smem/reg limits at the mandatory occupancy 2).
// ============================================================================
#define HID   4096
#define INTER 11008
#define MTOK  8192

// ============================================================================
// Device scratch (allocation rule: __device__ globals only)
// ============================================================================
__device__ __half g_x16 [(size_t)MTOK  * HID];     //  64 MB
__device__ __half g_wg16[(size_t)INTER * HID];     //  86 MB
__device__ __half g_wu16[(size_t)INTER * HID];     //  86 MB
__device__ __half g_wd16[(size_t)HID   * INTER];   //  86 MB
__device__ __half g_h16 [(size_t)MTOK  * INTER];   // 172 MB

// ============================================================================
// PTX helpers (sm_100-baseline: cp.async, ldmatrix, mma.sync)
// ============================================================================
__device__ __forceinline__ uint32_t smem_u32(const void* p) {
    uint32_t a;
    asm("{ .reg .u64 t; cvta.to.shared.u64 t, %1; cvt.u32.u64 %0, t; }"
        : "=r"(a) : "l"(p));
    return a;
}

__device__ __forceinline__ void cp_async16(uint32_t s, const void* g) {
    asm volatile("cp.async.cg.shared.global [%0], [%1], 16;" :: "r"(s), "l"(g));
}
#define CP_COMMIT() asm volatile("cp.async.commit_group;" ::: "memory")
#define CP_WAIT1()  asm volatile("cp.async.wait_group 1;"  ::: "memory")

__device__ __forceinline__ void ldsm4(uint32_t* r, uint32_t addr) {
    asm volatile("ldmatrix.sync.aligned.m8n8.x4.shared.b16 {%0,%1,%2,%3}, [%4];"
        : "=r"(r[0]), "=r"(r[1]), "=r"(r[2]), "=r"(r[3]) : "r"(addr));
}

__device__ __forceinline__ void mma16816(float* c, const uint32_t* a,
                                         uint32_t b0, uint32_t b1) {
    asm volatile(
        "mma.sync.aligned.m16n8k16.row.col.f32.f16.f16.f32 "
        "{%0,%1,%2,%3}, {%4,%5,%6,%7}, {%8,%9}, {%0,%1,%2,%3};"
        : "+f"(c[0]), "+f"(c[1]), "+f"(c[2]), "+f"(c[3])
        : "r"(a[0]), "r"(a[1]), "r"(a[2]), "r"(a[3]), "r"(b0), "r"(b1));
}

// ============================================================================
// Tile loader: R rows x 64 halves (128 B) per row, XOR-swizzled smem layout.
// smem_off = row*128 + ((chunk ^ (row&7)) << 4). Conflict-free for both the
// cp.async stores and ldmatrix reads. Verified correct R4-R10.
// ============================================================================
template<int THREADS, int R>
__device__ __forceinline__ void load_tile(uint32_t sbase, const __half* g,
                                          int row0, int k0, int ldk) {
    int t = threadIdx.x;
    #pragma unroll
    for (int i = 0; i < R * 8 / THREADS; i++) {
        int ch = t + i * THREADS;
        int r = ch >> 3, c = ch & 7;
        cp_async16(sbase + r * 128 + (uint32_t)((c ^ (r & 7)) << 4),
                   g + (size_t)(row0 + r) * ldk + k0 + c * 8);
    }
}

__device__ __forceinline__ float sigmoidf_fast(float v) {
    return 1.0f / (1.0f + __expf(-v));
}

__device__ __forceinline__ uint2 cvt4(const float4 v) {
    __half2 lo = __floats2half2_rn(v.x, v.y);
    __half2 hi = __floats2half2_rn(v.z, v.w);
    uint2 o;
    o.x = *reinterpret_cast<const uint32_t*>(&lo);
    o.y = *reinterpret_cast<const uint32_t*>(&hi);
    return o;
}

// ============================================================================
// Fused gate+up GEMM + SwiGLU, with embedded Wd converter.
// Grid: dim3(64, 173). blockIdx.y == 0 -> 64 cvt CTAs (first wave) converting
// Wd fp32->fp16 concurrently with the GEMM; y >= 1 -> GEMM n-tile (y-1).
// GEMM: CTA tile 128(M) x 64(N), 256 thr = 8 warps (4m x 2n), warp 32x32 per
// matrix, 3-stage cp.async (96 KB -> 2 CTAs/SM), smem-staged epilogue.
// ============================================================================
#define STG1 32768u
#define SMEM1 (3 * 32768)
#define EP1_STRIDE 144u

__global__ void __launch_bounds__(256, 2)
gemm1_fused(const __half* __restrict__ X, const __half* __restrict__ WG,
            const __half* __restrict__ WU, const float* __restrict__ ag,
            const float* __restrict__ au, __half* __restrict__ H,
            const float* __restrict__ WDf, __half* __restrict__ WDh) {
    // ---- embedded Wd converter: 64 CTAs, first wave, no smem/tensor use ----
    if (blockIdx.y == 0) {
        const size_t n4 = (size_t)HID * INTER / 4;           // 11272192 float4
        const size_t i0 = ((size_t)blockIdx.x * 256 + threadIdx.x) * 4;
        const float4* src = reinterpret_cast<const float4*>(WDf);
        uint2* dst = reinterpret_cast<uint2*>(WDh);
        for (size_t i = i0; i < n4; i += (size_t)16384 * 4) {
            #pragma unroll
            for (int j = 0; j < 4; j++)                       // MLP=4
                dst[i + j] = cvt4(src[i + j]);
        }
        return;
    }

    extern __shared__ char smem[];
    const uint32_t sb = smem_u32(smem);
    const int m0 = blockIdx.x * 128;
    const int n0 = (blockIdx.y - 1) * 64;
    const int l   = threadIdx.x & 31;
    const int wid = threadIdx.x >> 5;
    const int wm = (wid & 3) * 32;
    const int wn = (wid >> 2) * 32;
    const int KT = HID >> 6;

    #pragma unroll
    for (int s = 0; s < 2; s++) {
        uint32_t base = sb + (uint32_t)s * STG1;
        load_tile<256, 128>(base,           X,  m0, s * 64, HID);
        load_tile<256, 64> (base + 16384u,  WG, n0, s * 64, HID);
        load_tile<256, 64> (base + 24576u,  WU, n0, s * 64, HID);
        CP_COMMIT();
    }

    float accg[2][4][4], accu[2][4][4];
    #pragma unroll
    for (int i = 0; i < 2; i++)
        #pragma unroll
        for (int j = 0; j < 4; j++)
            #pragma unroll
            for (int q = 0; q < 4; q++) { accg[i][j][q] = 0.f; accu[i][j][q] = 0.f; }

    const int lr = l & 15, lc = l >> 4, lx = l & 7;

    int st = 0;
    for (int kt = 0; kt < KT; kt++) {
        CP_WAIT1();
        __syncthreads();
        if (kt + 2 < KT) {
            uint32_t base2 = sb + (uint32_t)((kt + 2) % 3) * STG1;
            load_tile<256, 128>(base2,          X,  m0, (kt + 2) * 64, HID);
            load_tile<256, 64> (base2 + 16384u, WG, n0, (kt + 2) * 64, HID);
            load_tile<256, 64> (base2 + 24576u, WU, n0, (kt + 2) * 64, HID);
        }
        CP_COMMIT();

        const uint32_t a_base = sb + (uint32_t)st * STG1           + (uint32_t)(wm + lr) * 128u;
        const uint32_t g_base = sb + (uint32_t)st * STG1 + 16384u  + (uint32_t)(wn + lr) * 128u;
        const uint32_t u_base = sb + (uint32_t)st * STG1 + 24576u  + (uint32_t)(wn + lr) * 128u;

        #pragma unroll
        for (int ks = 0; ks < 4; ks++) {
            const uint32_t ca = (uint32_t)(((ks * 2 + lc) ^ lx) << 4);
            uint32_t av[2][4], bg[2][4], bu[2][4];
            ldsm4(av[0], a_base + ca);
            ldsm4(av[1], a_base + 2048u + ca);
            ldsm4(bg[0], g_base + ca);
            ldsm4(bg[1], g_base + 2048u + ca);
            ldsm4(bu[0], u_base + ca);
            ldsm4(bu[1], u_base + 2048u + ca);
            #pragma unroll
            for (int mt = 0; mt < 2; mt++)
                #pragma unroll
                for (int nb = 0; nb < 2; nb++) {
                    mma16816(accg[mt][nb * 2 + 0], av[mt], bg[nb][0], bg[nb][2]);
                    mma16816(accg[mt][nb * 2 + 1], av[mt], bg[nb][1], bg[nb][3]);
                    mma16816(accu[mt][nb * 2 + 0], av[mt], bu[nb][0], bu[nb][2]);
                    mma16816(accu[mt][nb * 2 + 1], av[mt], bu[nb][1], bu[nb][3]);
                }
        }
        if (++st == 3) st = 0;
    }

    // ---- SwiGLU epilogue: regs -> smem (padded) -> coalesced global ----
    __syncthreads();
    const int r0 = l >> 2, c0 = (l & 3) * 2;
    #pragma unroll
    for (int mt = 0; mt < 2; mt++) {
        int lrow = wm + mt * 16 + r0;
        #pragma unroll
        for (int nf = 0; nf < 4; nf++) {
            int lcol = wn + nf * 8 + c0;
            int gn = n0 + lcol;
            float sg0 = ag[gn], sg1 = ag[gn + 1];
            float su0 = au[gn], su1 = au[gn + 1];
            float* G = accg[mt][nf];
            float* U = accu[mt][nf];
            float g0 = G[0] * sg0, g1 = G[1] * sg1;
            float u0 = U[0] * su0, u1 = U[1] * su1;
            __half2 h01 = __floats2half2_rn(g0 * sigmoidf_fast(g0) * u0,
                                            g1 * sigmoidf_fast(g1) * u1);
            float g2 = G[2] * sg0, g3 = G[3] * sg1;
            float u2 = U[2] * su0, u3 = U[3] * su1;
            __half2 h23 = __floats2half2_rn(g2 * sigmoidf_fast(g2) * u2,
                                            g3 * sigmoidf_fast(g3) * u3);
            *reinterpret_cast<__half2*>(smem + (uint32_t)lrow * EP1_STRIDE + lcol * 2) = h01;
            *reinterpret_cast<__half2*>(smem + (uint32_t)(lrow + 8) * EP1_STRIDE + lcol * 2) = h23;
        }
    }
    __syncthreads();
    #pragma unroll
    for (int i = 0; i < 4; i++) {
        int ch = threadIdx.x + i * 256;
        int row = ch >> 3, c = ch & 7;
        uint4 v = *reinterpret_cast<const uint4*>(smem + (uint32_t)row * EP1_STRIDE + c * 16);
        *reinterpret_cast<uint4*>(H + (size_t)(m0 + row) * INTER + n0 + c * 8) = v;
    }
}

// ============================================================================
// GEMM2: out[m,n] = (sum_k h[m,k] * Wd[n,k]) * ad[n], fp32 out.  (R10 config.)
// CTA 128x128, 256 threads / 8 warps (4m x 2n), warp tile 32x64.
// 3 stages x 32 KB = 96 KB -> 2 CTAs/SM. Coalesced smem-staged epilogue.
// Grid: x = n-tile (fast) so Wd (86 MB) stays L2-resident; h streams once.
// ============================================================================
#define STG2 32768u
#define SMEM2 (3 * 32768)
#define EP2_STRIDE 528u

__global__ void __launch_bounds__(256, 2)
gemm2_kernel(const __half* __restrict__ A, const __half* __restrict__ B,
             const float* __restrict__ ad, float* __restrict__ out) {
    extern __shared__ char smem[];
    const uint32_t sb = smem_u32(smem);
    const int n0 = blockIdx.x * 128;
    const int m0 = blockIdx.y * 128;
    const int l   = threadIdx.x & 31;
    const int wid = threadIdx.x >> 5;
    const int wm = (wid & 3) * 32;
    const int wn = (wid >> 2) * 64;
    const int KT = INTER >> 6;            // 172

    #pragma unroll
    for (int s = 0; s < 2; s++) {
        uint32_t base = sb + (uint32_t)s * STG2;
        load_tile<256, 128>(base,          A, m0, s * 64, INTER);
        load_tile<256, 128>(base + 16384u, B, n0, s * 64, INTER);
        CP_COMMIT();
    }

    float acc[2][8][4];
    #pragma unroll
    for (int i = 0; i < 2; i++)
        #pragma unroll
        for (int j = 0; j < 8; j++)
            #pragma unroll
            for (int q = 0; q < 4; q++) acc[i][j][q] = 0.f;

    const int lr = l & 15, lc = l >> 4, lx = l & 7;

    int st = 0;
    for (int kt = 0; kt < KT; kt++) {
        CP_WAIT1();
        __syncthreads();
        if (kt + 2 < KT) {
            uint32_t base2 = sb + (uint32_t)((kt + 2) % 3) * STG2;
            load_tile<256, 128>(base2,          A, m0, (kt + 2) * 64, INTER);
            load_tile<256, 128>(base2 + 16384u, B, n0, (kt + 2) * 64, INTER);
        }
        CP_COMMIT();

        const uint32_t a_base = sb + (uint32_t)st * STG2          + (uint32_t)(wm + lr) * 128u;
        const uint32_t b_base = sb + (uint32_t)st * STG2 + 16384u + (uint32_t)(wn + lr) * 128u;

        #pragma unroll
        for (int ks = 0; ks < 4; ks++) {
            const uint32_t ca = (uint32_t)(((ks * 2 + lc) ^ lx) << 4);
            uint32_t av[2][4], bv[4][4];
            ldsm4(av[0], a_base + ca);
            ldsm4(av[1], a_base + 2048u + ca);
            #pragma unroll
            for (int nb = 0; nb < 4; nb++)
                ldsm4(bv[nb], b_base + (uint32_t)nb * 2048u + ca);
            #pragma unroll
            for (int mt = 0; mt < 2; mt++)
                #pragma unroll
                for (int nb = 0; nb < 4; nb++) {
                    mma16816(acc[mt][nb * 2 + 0], av[mt], bv[nb][0], bv[nb][2]);
                    mma16816(acc[mt][nb * 2 + 1], av[mt], bv[nb][1], bv[nb][3]);
                }
        }
        if (++st == 3) st = 0;
    }

    // ---- epilogue: regs -> smem (padded) -> coalesced global ----
    __syncthreads();
    const int r0 = l >> 2, c0 = (l & 3) * 2;
    #pragma unroll
    for (int mt = 0; mt < 2; mt++) {
        int lrow = wm + mt * 16 + r0;
        #pragma unroll
        for (int nf = 0; nf < 8; nf++) {
            int lcol = wn + nf * 8 + c0;
            int gn = n0 + lcol;
            float s0 = ad[gn], s1 = ad[gn + 1];
            float* a4 = acc[mt][nf];
            *reinterpret_cast<float2*>(smem + (uint32_t)lrow * EP2_STRIDE + lcol * 4) =
                make_float2(a4[0] * s0, a4[1] * s1);
            *reinterpret_cast<float2*>(smem + (uint32_t)(lrow + 8) * EP2_STRIDE + lcol * 4) =
                make_float2(a4[2] * s0, a4[3] * s1);
        }
    }
    __syncthreads();
    #pragma unroll
    for (int i = 0; i < 16; i++) {
        int ch = threadIdx.x + i * 256;
        int row = ch >> 5, c = ch & 31;
        uint4 v = *reinterpret_cast<const uint4*>(smem + (uint32_t)row * EP2_STRIDE + c * 16);
        *reinterpret_cast<uint4*>(out + (size_t)(m0 + row) * HID + n0 + c * 4) = v;
    }
}

// ============================================================================
// fp32 -> fp16 conversion for x, Wg, Wu (GEMM1 prerequisites; Wd is embedded
// in the gemm1 launch).
// ============================================================================
__global__ void cvt3(const float* __restrict__ i0, __half* __restrict__ o0, size_t n0,
                     const float* __restrict__ i1, __half* __restrict__ o1, size_t n1,
                     const float* __restrict__ i2, __half* __restrict__ o2, size_t n2) {
    const size_t stride = (size_t)gridDim.x * blockDim.x;
    const size_t t0 = (size_t)blockIdx.x * blockDim.x + threadIdx.x;
    const float*  in[3]   = {i0, i1, i2};
    __half*       outp[3] = {o0, o1, o2};
    const size_t  n[3]    = {n0, n1, n2};
    #pragma unroll
    for (int s = 0; s < 3; s++) {
        const float* src = in[s];
        __half* dst = outp[s];
        for (size_t i = t0; i < n[s]; i += stride) {
            uint2 o = cvt4(reinterpret_cast<const float4*>(src)[i]);
            reinterpret_cast<uint2*>(dst)[i] = o;
        }
    }
}

// ============================================================================
// Host side — single stream, pure kernel launches (graph-capture safe).
// ============================================================================
extern "C" void kernel_launch(void* const* d_in, const int* in_sizes, int n_in,
                              void* d_out, int out_size) {
    const float* x  = (const float*)d_in[0];
    const float* Wg = (const float*)d_in[1];
    const float* Wu = (const float*)d_in[2];
    const float* Wd = (const float*)d_in[3];
    const float* ag = (const float*)d_in[4];
    const float* au = (const float*)d_in[5];
    const float* ad = (const float*)d_in[6];
    float* out = (float*)d_out;

    void *px, *pwg, *pwu, *pwd, *ph;
    cudaGetSymbolAddress(&px,  g_x16);
    cudaGetSymbolAddress(&pwg, g_wg16);
    cudaGetSymbolAddress(&pwu, g_wu16);
    cudaGetSymbolAddress(&pwd, g_wd16);
    cudaGetSymbolAddress(&ph,  g_h16);

    cudaFuncSetAttribute(gemm1_fused,
                         cudaFuncAttributeMaxDynamicSharedMemorySize, SMEM1);
    cudaFuncSetAttribute(gemm2_kernel,
                         cudaFuncAttributeMaxDynamicSharedMemorySize, SMEM2);

    // fp32 -> fp16 for GEMM1's inputs only (Wd converts inside gemm1 launch)
    cvt3<<<3072, 256>>>(
        x,  (__half*)px,  (size_t)MTOK  * HID / 4,
        Wg, (__half*)pwg, (size_t)INTER * HID / 4,
        Wu, (__half*)pwu, (size_t)INTER * HID / 4);

    // Fused gate+up+SwiGLU -> h (fp16), plus 64 embedded Wd-cvt CTAs (y==0).
    gemm1_fused<<<dim3(MTOK / 128, INTER / 64 + 1), 256, SMEM1>>>(
        (const __half*)px, (const __half*)pwg, (const __half*)pwu,
        ag, au, (__half*)ph, Wd, (__half*)pwd);

    // out = (h @ Wd^T) * ad. n-tiles fast (Wd L2-resident).
    gemm2_kernel<<<dim3(HID / 128, MTOK / 128), 256, SMEM2>>>(
        (const __half*)ph, (const __half*)pwd, ad, out);
}